// round 7
// baseline (speedup 1.0000x reference)
#include <cuda_runtime.h>
#include <math.h>

// Problem constants
#define T_STEPS 16384
#define HID     1024
#define INP     256
#define NLAB    32

#define NCTA    128          // persistent CTAs, one per SM, single wave
#define WPC     8            // warps per CTA; NCTA*WPC == HID rows (1 warp : 1 row)
#define TPB     (WPC * 32)   // 256
#define WPT     (HID / TPB)  // tagged words polled per thread = 4

// Tagged hidden state: word = (float_bits(h) << 32) | step_tag.
// Double-buffered by step parity; a single relaxed 64-bit store publishes
// value+tag atomically -> no fences anywhere. All tagged-word traffic (global
// AND shared) uses relaxed atomics: morally-strong <=64b ops are single-copy
// atomic, so tag+value can never tear. Reset kernel restores tags each launch
// so graph replays are deterministic.
__device__ unsigned long long g_hbuf[2][HID];

__device__ __forceinline__ unsigned long long ldx(const unsigned long long* p) {
    unsigned long long v;
    asm volatile("ld.relaxed.gpu.global.b64 %0, [%1];" : "=l"(v) : "l"(p));
    return v;
}
__device__ __forceinline__ void stx(unsigned long long* p, unsigned long long v) {
    asm volatile("st.relaxed.gpu.global.b64 [%0], %1;" :: "l"(p), "l"(v) : "memory");
}
__device__ __forceinline__ unsigned long long packh(float h, unsigned tag) {
    return ((unsigned long long)__float_as_uint(h) << 32) | (unsigned long long)tag;
}
__device__ __forceinline__ float unpackh(unsigned long long v) {
    return __uint_as_float((unsigned)(v >> 32));
}
__device__ __forceinline__ float tanh_fast(float v) {
    float r;
    asm volatile("tanh.approx.f32 %0, %1;" : "=f"(r) : "f"(v));
    return r;
}
__device__ __forceinline__ unsigned saddr(const void* p) {
    return (unsigned)__cvta_generic_to_shared(p);
}
// Tearing-proof SMEM tagged-word ops (relaxed atomics, cta scope).
__device__ __forceinline__ void sts_rlx(unsigned a, unsigned long long v) {
    asm volatile("st.relaxed.cta.shared.u64 [%0], %1;" :: "r"(a), "l"(v) : "memory");
}
__device__ __forceinline__ unsigned long long lds_rlx(unsigned a) {
    unsigned long long v;
    asm volatile("ld.relaxed.cta.shared.u64 %0, [%1];" : "=l"(v) : "r"(a));
    return v;
}

__global__ void rnn_reset_kernel() {
    int t = threadIdx.x;
    unsigned long long z = packh(0.0f, 0u);   // h0 = 0, tag 0
    for (int i = t; i < 2 * HID; i += blockDim.x)
        ((unsigned long long*)g_hbuf)[i] = z;
}

__global__ void __launch_bounds__(TPB, 1) rnn_scan_kernel(
    const float* __restrict__ X,    // [T, 1, 256]
    const float* __restrict__ Wi,   // [1024, 256]
    const float* __restrict__ bi,   // [1024]
    const float* __restrict__ Wh,   // [1024, 1024]
    const float* __restrict__ bh,   // [1024]
    const float* __restrict__ Wo,   // [32, 1024]
    const float* __restrict__ bo,   // [32]
    float* __restrict__ out)        // [32] log-softmax
{
    const int t    = threadIdx.x;
    const int lane = t & 31;
    const int warp = t >> 5;
    const int row  = blockIdx.x * WPC + warp;   // this warp's hidden row

    // Double-buffered TAGGED h staged per CTA (dataflow; no per-step barrier).
    __shared__ unsigned long long stag[2][HID];
    __shared__ float shE[HID];   // epilogue scratch

    // Sentinel tags so step-0/1 consumers never accept garbage.
    for (int i = t; i < 2 * HID; i += TPB)
        ((unsigned long long*)stag)[i] = 0xFFFFFFFFull;

    // ---- Register-resident weights (held for all 16384 steps) ----
    // Warp-rotated group ownership: slot g of this warp covers hidden column
    // group pg = (g + warp) & 7, columns pg*128 + 4*lane + (0..3). Rotation
    // spreads which SMEM words each warp waits on (no convoy), while keeping
    // all register indices static.
    float w[32];
    #pragma unroll
    for (int g = 0; g < 8; g++) {
        int pg = (g + warp) & 7;
        #pragma unroll
        for (int j = 0; j < 4; j++)
            w[4 * g + j] = Wh[row * HID + pg * 128 + 4 * lane + j];
    }
    float wi[8];
    #pragma unroll
    for (int k = 0; k < 8; k++)
        wi[k] = Wi[row * INP + (k >> 2) * 128 + 4 * lane + (k & 3)];
    const float bias = bi[row] + bh[row];

    __syncthreads();   // sentinel init visible to all warps (once, pre-loop)

    // ---- 3-deep input pipeline: x0 = step s, x1 = step s+1 ----
    const float4* X4 = (const float4*)X;
    float4 x0a = X4[lane];            float4 x0b = X4[32 + lane];
    float4 x1a = X4[64 + lane];       float4 x1b = X4[96 + lane];

    const unsigned sfill0 = saddr(&stag[0][t]);        // this thread's fill slot
    const unsigned scons0 = saddr(&stag[0][4 * lane]); // this lane's read base

    for (int s = 0; s < T_STEPS; s++) {
        const int buf = s & 1;
        const unsigned tag = (unsigned)s;
        const unsigned long long* hb = g_hbuf[buf];
        const unsigned sfill = sfill0 + buf * (HID * 8);
        const unsigned scons = scons0 + buf * (HID * 8);

        // ---- Fill: poll own 4 global words; deposit each as it resolves. ----
        unsigned long long v[WPT];
        #pragma unroll
        for (int i = 0; i < WPT; i++) v[i] = ldx(hb + t + TPB * i);

        // Prefetch x for step s+2 (two step-periods of DRAM cover).
        float4 x2a, x2b;
        x2a.x = x2a.y = x2a.z = x2a.w = 0.f;
        x2b = x2a;
        if (s + 2 < T_STEPS) {
            x2a = X4[(s + 2) * 64 + lane];
            x2b = X4[(s + 2) * 64 + 32 + lane];
        }

        // Input projection for THIS step while polls are in flight.
        float a0 = (lane == 0) ? bias : 0.0f;
        float a1 = 0.f, a2 = 0.f, a3 = 0.f;
        a0 = fmaf(wi[0], x0a.x, a0);  a1 = fmaf(wi[1], x0a.y, a1);
        a2 = fmaf(wi[2], x0a.z, a2);  a3 = fmaf(wi[3], x0a.w, a3);
        a0 = fmaf(wi[4], x0b.x, a0);  a1 = fmaf(wi[5], x0b.y, a1);
        a2 = fmaf(wi[6], x0b.z, a2);  a3 = fmaf(wi[7], x0b.w, a3);

        unsigned pend = (1u << WPT) - 1u;
        do {
            #pragma unroll
            for (int i = 0; i < WPT; i++) {
                if (pend & (1u << i)) {
                    if ((unsigned)v[i] == tag) {
                        sts_rlx(sfill + i * (TPB * 8), v[i]);
                        pend &= ~(1u << i);
                    } else {
                        v[i] = ldx(hb + t + TPB * i);
                    }
                }
            }
        } while (pend);

        // ---- Consume: FMA each column group as soon as it is ready. ----
        #pragma unroll
        for (int g = 0; g < 8; g++) {
            int pg = (g + warp) & 7;               // matches weight layout
            unsigned a = scons + (unsigned)pg * (128 * 8);
            unsigned long long p0, p1, q0, q1;
            for (;;) {
                p0 = lds_rlx(a);
                p1 = lds_rlx(a + 8);
                q0 = lds_rlx(a + 16);
                q1 = lds_rlx(a + 24);
                if ((((unsigned)p0 ^ tag) | ((unsigned)p1 ^ tag) |
                     ((unsigned)q0 ^ tag) | ((unsigned)q1 ^ tag)) == 0u) break;
            }
            a0 = fmaf(w[4 * g + 0], unpackh(p0), a0);
            a1 = fmaf(w[4 * g + 1], unpackh(p1), a1);
            a2 = fmaf(w[4 * g + 2], unpackh(q0), a2);
            a3 = fmaf(w[4 * g + 3], unpackh(q1), a3);
        }
        float acc = (a0 + a1) + (a2 + a3);
        #pragma unroll
        for (int off = 16; off > 0; off >>= 1)
            acc += __shfl_xor_sync(0xffffffffu, acc, off);

        if (lane == 0) {
            float hnew = tanh_fast(acc);
            stx(&g_hbuf[buf ^ 1][row], packh(hnew, tag + 1u));
        }

        x0a = x1a; x0b = x1b;
        x1a = x2a; x1b = x2b;
    }

    // ---- Epilogue: CTA 0 computes logits + log_softmax on h_T ----
    if (blockIdx.x == 0) {
        __syncthreads();   // quiesce scan-phase SMEM traffic
        for (int j = t; j < HID; j += TPB) {
            unsigned long long vv = ldx(&g_hbuf[0][j]);   // T even -> buffer 0
            while (((unsigned)vv) != (unsigned)T_STEPS) vv = ldx(&g_hbuf[0][j]);
            shE[j] = unpackh(vv);
        }
        __syncthreads();

        int orow = t >> 3;      // 32 rows x 8 threads
        int sub  = t & 7;
        float acc = 0.0f;
        #pragma unroll 4
        for (int j = 0; j < HID / 8; j += 4) {
            int col = sub * (HID / 8) + j;
            float4 w4 = ((const float4*)Wo)[(orow * HID + col) >> 2];
            acc = fmaf(w4.x, shE[col + 0], acc);
            acc = fmaf(w4.y, shE[col + 1], acc);
            acc = fmaf(w4.z, shE[col + 2], acc);
            acc = fmaf(w4.w, shE[col + 3], acc);
        }
        acc += __shfl_down_sync(0xffffffffu, acc, 4);
        acc += __shfl_down_sync(0xffffffffu, acc, 2);
        acc += __shfl_down_sync(0xffffffffu, acc, 1);

        __shared__ float s_log[NLAB];
        if (sub == 0 && orow < NLAB) s_log[orow] = acc + bo[orow];
        __syncthreads();

        if (t < NLAB) {
            float vl = s_log[t];
            float m = vl;
            #pragma unroll
            for (int off = 16; off > 0; off >>= 1)
                m = fmaxf(m, __shfl_xor_sync(0xffffffffu, m, off));
            float e = expf(vl - m);
            float ssum = e;
            #pragma unroll
            for (int off = 16; off > 0; off >>= 1)
                ssum += __shfl_xor_sync(0xffffffffu, ssum, off);
            out[t] = vl - m - logf(ssum);
        }
    }
}

extern "C" void kernel_launch(void* const* d_in, const int* in_sizes, int n_in,
                              void* d_out, int out_size) {
    const float* X  = (const float*)d_in[0];
    const float* Wi = (const float*)d_in[1];
    const float* bi = (const float*)d_in[2];
    const float* Wh = (const float*)d_in[3];
    const float* bh = (const float*)d_in[4];
    const float* Wo = (const float*)d_in[5];
    const float* bo = (const float*)d_in[6];
    float* out = (float*)d_out;

    rnn_reset_kernel<<<1, 256>>>();
    rnn_scan_kernel<<<NCTA, TPB>>>(X, Wi, bi, Wh, bh, Wo, bo, out);
}

// round 8
// speedup vs baseline: 5.1992x; 5.1992x over previous
#include <cuda_runtime.h>
#include <math.h>

// Problem constants
#define T_STEPS 16384
#define HID     1024
#define INP     256
#define NLAB    32

#define NCTA    64           // persistent CTAs; halves redundant h fan-in vs 128
#define WPC     16           // warps per CTA; NCTA*WPC == HID rows (1 warp : 1 row)
#define TPB     (WPC * 32)   // 512
#define WPT     (HID / TPB)  // tagged words polled per thread = 2

// Tagged hidden state: word = (float_bits(h) << 32) | step_tag.
// Double-buffered by step parity; a single relaxed 64-bit GLOBAL store
// publishes value+tag atomically -> no fences anywhere. SMEM staging holds
// plain floats and is ordered by one __syncthreads per step (R5-proven).
__device__ unsigned long long g_hbuf[2][HID];

__device__ __forceinline__ unsigned long long ldx(const unsigned long long* p) {
    unsigned long long v;
    asm volatile("ld.relaxed.gpu.global.b64 %0, [%1];" : "=l"(v) : "l"(p));
    return v;
}
__device__ __forceinline__ void stx(unsigned long long* p, unsigned long long v) {
    asm volatile("st.relaxed.gpu.global.b64 [%0], %1;" :: "l"(p), "l"(v) : "memory");
}
__device__ __forceinline__ unsigned long long packh(float h, unsigned tag) {
    return ((unsigned long long)__float_as_uint(h) << 32) | (unsigned long long)tag;
}
__device__ __forceinline__ float unpackh(unsigned long long v) {
    return __uint_as_float((unsigned)(v >> 32));
}
__device__ __forceinline__ float tanh_fast(float v) {
    float r;
    asm volatile("tanh.approx.f32 %0, %1;" : "=f"(r) : "f"(v));
    return r;
}

__global__ void rnn_reset_kernel() {
    int t = threadIdx.x;
    unsigned long long z = packh(0.0f, 0u);   // h0 = 0, tag 0
    for (int i = t; i < 2 * HID; i += blockDim.x)
        ((unsigned long long*)g_hbuf)[i] = z;
}

__global__ void __launch_bounds__(TPB, 1) rnn_scan_kernel(
    const float* __restrict__ X,    // [T, 1, 256]
    const float* __restrict__ Wi,   // [1024, 256]
    const float* __restrict__ bi,   // [1024]
    const float* __restrict__ Wh,   // [1024, 1024]
    const float* __restrict__ bh,   // [1024]
    const float* __restrict__ Wo,   // [32, 1024]
    const float* __restrict__ bo,   // [32]
    float* __restrict__ out)        // [32] log-softmax
{
    const int t    = threadIdx.x;
    const int lane = t & 31;
    const int warp = t >> 5;
    const int row  = blockIdx.x * WPC + warp;   // this warp's hidden row

    // Double-buffered plain-float h staged per CTA. One barrier per step.
    __shared__ float sh[2][HID];

    // ---- Register-resident weights (held for all 16384 steps) ----
    // Lane l owns hidden columns (k/4)*128 + 4l + (k%4), k=0..31  (float4-
    // contiguous groups -> 8x LDS.128 per step) and the analogous 8 input cols.
    float w[32];
    #pragma unroll
    for (int k = 0; k < 32; k++)
        w[k] = Wh[row * HID + (k >> 2) * 128 + 4 * lane + (k & 3)];
    float wi[8];
    #pragma unroll
    for (int k = 0; k < 8; k++)
        wi[k] = Wi[row * INP + (k >> 2) * 128 + 4 * lane + (k & 3)];
    const float bias = bi[row] + bh[row];

    // ---- 3-deep input pipeline: x0 = step s, x1 = step s+1 ----
    const float4* X4 = (const float4*)X;   // step s slice at X4[s*64 + ...]
    float4 x0a = X4[lane];            float4 x0b = X4[32 + lane];
    float4 x1a = X4[64 + lane];       float4 x1b = X4[96 + lane];

    for (int s = 0; s < T_STEPS; s++) {
        const int buf = s & 1;
        const unsigned tag = (unsigned)s;
        const unsigned long long* hb = g_hbuf[buf];

        // ---- Poll phase: this CTA reads global h exactly once (8KB). ----
        // Thread t owns words {t, t+512}. Issue both, retry stale only.
        unsigned long long v0 = ldx(hb + t);
        unsigned long long v1 = ldx(hb + t + TPB);

        // Prefetch x for step s+2 (two step-periods of DRAM cover).
        float4 x2a, x2b;
        x2a.x = x2a.y = x2a.z = x2a.w = 0.f;
        x2b = x2a;
        if (s + 2 < T_STEPS) {
            x2a = X4[(s + 2) * 64 + lane];
            x2b = X4[(s + 2) * 64 + 32 + lane];
        }

        // Input projection for THIS step while polls are in flight.
        float a0 = (lane == 0) ? bias : 0.0f;
        float a1 = 0.f, a2 = 0.f, a3 = 0.f;
        a0 = fmaf(wi[0], x0a.x, a0);  a1 = fmaf(wi[1], x0a.y, a1);
        a2 = fmaf(wi[2], x0a.z, a2);  a3 = fmaf(wi[3], x0a.w, a3);
        a0 = fmaf(wi[4], x0b.x, a0);  a1 = fmaf(wi[5], x0b.y, a1);
        a2 = fmaf(wi[6], x0b.z, a2);  a3 = fmaf(wi[7], x0b.w, a3);

        // Resolve tags: retry only stale words (tags monotone, <= s).
        while ((((unsigned)v0) ^ tag) | (((unsigned)v1) ^ tag)) {
            if ((unsigned)v0 != tag) v0 = ldx(hb + t);
            if ((unsigned)v1 != tag) v1 = ldx(hb + t + TPB);
        }
        sh[buf][t]       = unpackh(v0);
        sh[buf][t + TPB] = unpackh(v1);

        __syncthreads();   // the only barrier per step

        // ---- Recurrent GEMV: 8x LDS.128 + 32 FMA. ----
        const float* hs = sh[buf];
        #pragma unroll
        for (int g = 0; g < 8; g++) {
            float4 h4 = *(const float4*)(hs + g * 128 + 4 * lane);
            a0 = fmaf(w[4 * g + 0], h4.x, a0);
            a1 = fmaf(w[4 * g + 1], h4.y, a1);
            a2 = fmaf(w[4 * g + 2], h4.z, a2);
            a3 = fmaf(w[4 * g + 3], h4.w, a3);
        }
        float acc = (a0 + a1) + (a2 + a3);
        #pragma unroll
        for (int off = 16; off > 0; off >>= 1)
            acc += __shfl_xor_sync(0xffffffffu, acc, off);

        if (lane == 0) {
            float hnew = tanh_fast(acc);
            stx(&g_hbuf[buf ^ 1][row], packh(hnew, tag + 1u));
        }

        x0a = x1a; x0b = x1b;
        x1a = x2a; x1b = x2b;
    }

    // ---- Epilogue: CTA 0 computes logits + log_softmax on h_T ----
    if (blockIdx.x == 0) {
        for (int j = t; j < HID; j += TPB) {
            unsigned long long vv = ldx(&g_hbuf[0][j]);   // T even -> buffer 0
            while (((unsigned)vv) != (unsigned)T_STEPS) vv = ldx(&g_hbuf[0][j]);
            sh[0][j] = unpackh(vv);
        }
        __syncthreads();

        if (t < 256) {
            int orow = t >> 3;      // 32 rows x 8 threads
            int sub  = t & 7;
            float acc = 0.0f;
            #pragma unroll 4
            for (int j = 0; j < HID / 8; j += 4) {
                int col = sub * (HID / 8) + j;
                float4 w4 = ((const float4*)Wo)[(orow * HID + col) >> 2];
                acc = fmaf(w4.x, sh[0][col + 0], acc);
                acc = fmaf(w4.y, sh[0][col + 1], acc);
                acc = fmaf(w4.z, sh[0][col + 2], acc);
                acc = fmaf(w4.w, sh[0][col + 3], acc);
            }
            acc += __shfl_down_sync(0xffffffffu, acc, 4);
            acc += __shfl_down_sync(0xffffffffu, acc, 2);
            acc += __shfl_down_sync(0xffffffffu, acc, 1);

            __shared__ float s_log[NLAB];
            if (sub == 0) s_log[orow] = acc + bo[orow];
            __syncwarp();
            // ensure all 8 producer warps' s_log writes are visible
            __threadfence_block();
        }
        __syncthreads();

        if (t < NLAB) {
            __shared__ float s_log2[NLAB];   // alias-free reread via shared
            // read logits staged by the t<256 section
            extern __shared__ float dummy[];
            (void)dummy;
            float vl;
            {
                // s_log was declared in the t<256 scope; re-declare accessor
                // by recomputing: simplest is to recompute via shared mem is
                // not possible across scopes -> use global-less approach:
                vl = 0.0f;
            }
            // NOTE: handled below
            (void)s_log2; (void)vl;
        }
        // --- flat re-implementation to avoid scope issues ---
        __shared__ float s_logF[NLAB];
        if (t < 256) {
            int orow = t >> 3;
            int sub  = t & 7;
            float acc = 0.0f;
            #pragma unroll 4
            for (int j = 0; j < HID / 8; j += 4) {
                int col = sub * (HID / 8) + j;
                float4 w4 = ((const float4*)Wo)[(orow * HID + col) >> 2];
                acc = fmaf(w4.x, sh[0][col + 0], acc);
                acc = fmaf(w4.y, sh[0][col + 1], acc);
                acc = fmaf(w4.z, sh[0][col + 2], acc);
                acc = fmaf(w4.w, sh[0][col + 3], acc);
            }
            acc += __shfl_down_sync(0xffffffffu, acc, 4);
            acc += __shfl_down_sync(0xffffffffu, acc, 2);
            acc += __shfl_down_sync(0xffffffffu, acc, 1);
            if (sub == 0) s_logF[orow] = acc + bo[orow];
        }
        __syncthreads();

        if (t < NLAB) {
            float vl = s_logF[t];
            float m = vl;
            #pragma unroll
            for (int off = 16; off > 0; off >>= 1)
                m = fmaxf(m, __shfl_xor_sync(0xffffffffu, m, off));
            float e = expf(vl - m);
            float ssum = e;
            #pragma unroll
            for (int off = 16; off > 0; off >>= 1)
                ssum += __shfl_xor_sync(0xffffffffu, ssum, off);
            out[t] = vl - m - logf(ssum);
        }
    }
}

extern "C" void kernel_launch(void* const* d_in, const int* in_sizes, int n_in,
                              void* d_out, int out_size) {
    const float* X  = (const float*)d_in[0];
    const float* Wi = (const float*)d_in[1];
    const float* bi = (const float*)d_in[2];
    const float* Wh = (const float*)d_in[3];
    const float* bh = (const float*)d_in[4];
    const float* Wo = (const float*)d_in[5];
    const float* bo = (const float*)d_in[6];
    float* out = (float*)d_out;

    rnn_reset_kernel<<<1, 256>>>();
    rnn_scan_kernel<<<NCTA, TPB>>>(X, Wi, bi, Wh, bh, Wo, bo, out);
}

// round 9
// speedup vs baseline: 8.7732x; 1.6874x over previous
#include <cuda_runtime.h>
#include <math.h>

// Problem constants
#define T_STEPS 16384
#define HID     1024
#define INP     256
#define NLAB    32

#define NCTA    128          // persistent CTAs, one per SM, single wave
#define WPC     8            // warps per CTA; NCTA*WPC == HID rows (1 warp : 1 row)
#define TPB     (WPC * 32)   // 256
#define WPT     (HID / TPB)  // tagged words polled per thread = 4

// Hidden state words: fp32 h with its mantissa LSB carrying a 1-bit step tag
// tau(s) = (s>>1)&1. Double-buffered by parity s&1; stale content in a buffer
// is from step s-2, whose tau differs -> LSB equality == ready. One relaxed
// 4B store publishes value+tag atomically; no fences anywhere. LSB clobber
// perturbs h by <=2^-23 relative (absorbed by the contractive recurrence).
// Reset kernel restores both buffers each launch (graph-replay determinism).
__device__ unsigned g_hbuf[2][HID];

__device__ __forceinline__ unsigned ldx32(const unsigned* p) {
    unsigned v;
    asm volatile("ld.relaxed.gpu.global.u32 %0, [%1];" : "=r"(v) : "l"(p));
    return v;
}
__device__ __forceinline__ void stx32(unsigned* p, unsigned v) {
    asm volatile("st.relaxed.gpu.global.u32 [%0], %1;" :: "l"(p), "r"(v) : "memory");
}
__device__ __forceinline__ float tanh_fast(float v) {
    float r;
    asm volatile("tanh.approx.f32 %0, %1;" : "=f"(r) : "f"(v));
    return r;
}

__global__ void rnn_reset_kernel() {
    int t = threadIdx.x;
    for (int i = t; i < HID; i += blockDim.x) {
        g_hbuf[0][i] = 0u;   // h0 = 0.0f, LSB 0 == tau(0): valid for step 0
        g_hbuf[1][i] = 1u;   // LSB 1 != tau(1)=0: step-1 consumers must wait
    }
}

__global__ void __launch_bounds__(TPB, 1) rnn_scan_kernel(
    const float* __restrict__ X,    // [T, 1, 256]
    const float* __restrict__ Wi,   // [1024, 256]
    const float* __restrict__ bi,   // [1024]
    const float* __restrict__ Wh,   // [1024, 1024]
    const float* __restrict__ bh,   // [1024]
    const float* __restrict__ Wo,   // [32, 1024]
    const float* __restrict__ bo,   // [32]
    float* __restrict__ out)        // [32] log-softmax
{
    const int t    = threadIdx.x;
    const int lane = t & 31;
    const int warp = t >> 5;
    const int row  = blockIdx.x * WPC + warp;   // this warp's hidden row

    // Double-buffered plain-float h staged per CTA. One barrier per step.
    __shared__ float sh[2][HID];

    // ---- Register-resident weights (held for all 16384 steps) ----
    // Lane l owns hidden columns (k/4)*128 + 4l + (k%4), k=0..31 (float4-
    // contiguous groups -> 8x LDS.128 per step) and the analogous 8 input cols.
    float w[32];
    #pragma unroll
    for (int k = 0; k < 32; k++)
        w[k] = Wh[row * HID + (k >> 2) * 128 + 4 * lane + (k & 3)];
    float wi[8];
    #pragma unroll
    for (int k = 0; k < 8; k++)
        wi[k] = Wi[row * INP + (k >> 2) * 128 + 4 * lane + (k & 3)];
    const float bias = bi[row] + bh[row];

    // ---- Input pipeline: x0 = step s, x1 = step s+1 (x2 fetched in-loop) ----
    const float4* X4 = (const float4*)X;   // step s slice at X4[s*64 + ...]
    float4 x0a = X4[lane];            float4 x0b = X4[32 + lane];
    float4 x1a = X4[64 + lane];       float4 x1b = X4[96 + lane];

    for (int s = 0; s < T_STEPS; s++) {
        const int buf = s & 1;
        const unsigned tau = ((unsigned)s >> 1) & 1u;
        const unsigned* hb = g_hbuf[buf];

        // ---- Poll phase: issue all 4 word loads first (nothing queued
        // ahead of them); retry only stale words. 1 line per warp per ld. ----
        unsigned v[WPT];
        #pragma unroll
        for (int i = 0; i < WPT; i++) v[i] = ldx32(hb + t + TPB * i);

        // Input projection for THIS step while polls are in flight.
        float a0 = (lane == 0) ? bias : 0.0f;
        float a1 = 0.f, a2 = 0.f, a3 = 0.f;
        a0 = fmaf(wi[0], x0a.x, a0);  a1 = fmaf(wi[1], x0a.y, a1);
        a2 = fmaf(wi[2], x0a.z, a2);  a3 = fmaf(wi[3], x0a.w, a3);
        a0 = fmaf(wi[4], x0b.x, a0);  a1 = fmaf(wi[5], x0b.y, a1);
        a2 = fmaf(wi[6], x0b.z, a2);  a3 = fmaf(wi[7], x0b.w, a3);

        for (;;) {
            unsigned bad = 0;
            #pragma unroll
            for (int i = 0; i < WPT; i++) bad |= (v[i] ^ tau) & 1u;
            if (bad == 0) break;
            #pragma unroll
            for (int i = 0; i < WPT; i++)
                if ((v[i] & 1u) != tau) v[i] = ldx32(hb + t + TPB * i);
        }
        #pragma unroll
        for (int i = 0; i < WPT; i++)
            sh[buf][t + TPB * i] = __uint_as_float(v[i]);

        __syncthreads();   // the only barrier per step

        // Prefetch x for step s+2 AFTER the barrier: these DRAM loads never
        // sit between poll issue and poll retries. >1 full step of slack.
        {
            int sx = (s + 2 < T_STEPS) ? (s + 2) : (T_STEPS - 1);
            float4 x2a = X4[sx * 64 + lane];
            float4 x2b = X4[sx * 64 + 32 + lane];

            // ---- Recurrent GEMV: 8x LDS.128 + 32 FMA. ----
            const float* hs = sh[buf];
            #pragma unroll
            for (int g = 0; g < 8; g++) {
                float4 h4 = *(const float4*)(hs + g * 128 + 4 * lane);
                a0 = fmaf(w[4 * g + 0], h4.x, a0);
                a1 = fmaf(w[4 * g + 1], h4.y, a1);
                a2 = fmaf(w[4 * g + 2], h4.z, a2);
                a3 = fmaf(w[4 * g + 3], h4.w, a3);
            }
            float acc = (a0 + a1) + (a2 + a3);
            #pragma unroll
            for (int off = 16; off > 0; off >>= 1)
                acc += __shfl_xor_sync(0xffffffffu, acc, off);

            if (lane == 0) {
                float hnew = tanh_fast(acc);
                unsigned ub = (__float_as_uint(hnew) & ~1u) |
                              (((unsigned)(s + 1) >> 1) & 1u);
                stx32(&g_hbuf[buf ^ 1][row], ub);
            }

            x0a = x1a; x0b = x1b;
            x1a = x2a; x1b = x2b;
        }
    }

    // ---- Epilogue: CTA 0 computes logits + log_softmax on h_T ----
    if (blockIdx.x == 0) {
        const unsigned tauT = ((unsigned)T_STEPS >> 1) & 1u;   // buffer 0
        for (int j = t; j < HID; j += TPB) {
            unsigned vv = ldx32(&g_hbuf[0][j]);
            while ((vv & 1u) != tauT) vv = ldx32(&g_hbuf[0][j]);
            sh[0][j] = __uint_as_float(vv);
        }
        __syncthreads();

        int orow = t >> 3;      // 32 rows x 8 threads
        int sub  = t & 7;
        float acc = 0.0f;
        #pragma unroll 4
        for (int j = 0; j < HID / 8; j += 4) {
            int col = sub * (HID / 8) + j;
            float4 w4 = ((const float4*)Wo)[(orow * HID + col) >> 2];
            acc = fmaf(w4.x, sh[0][col + 0], acc);
            acc = fmaf(w4.y, sh[0][col + 1], acc);
            acc = fmaf(w4.z, sh[0][col + 2], acc);
            acc = fmaf(w4.w, sh[0][col + 3], acc);
        }
        acc += __shfl_down_sync(0xffffffffu, acc, 4);
        acc += __shfl_down_sync(0xffffffffu, acc, 2);
        acc += __shfl_down_sync(0xffffffffu, acc, 1);

        __shared__ float s_log[NLAB];
        if (sub == 0) s_log[orow] = acc + bo[orow];
        __syncthreads();

        if (t < NLAB) {
            float vl = s_log[t];
            float m = vl;
            #pragma unroll
            for (int off = 16; off > 0; off >>= 1)
                m = fmaxf(m, __shfl_xor_sync(0xffffffffu, m, off));
            float e = expf(vl - m);
            float ssum = e;
            #pragma unroll
            for (int off = 16; off > 0; off >>= 1)
                ssum += __shfl_xor_sync(0xffffffffu, ssum, off);
            out[t] = vl - m - logf(ssum);
        }
    }
}

extern "C" void kernel_launch(void* const* d_in, const int* in_sizes, int n_in,
                              void* d_out, int out_size) {
    const float* X  = (const float*)d_in[0];
    const float* Wi = (const float*)d_in[1];
    const float* bi = (const float*)d_in[2];
    const float* Wh = (const float*)d_in[3];
    const float* bh = (const float*)d_in[4];
    const float* Wo = (const float*)d_in[5];
    const float* bo = (const float*)d_in[6];
    float* out = (float*)d_out;

    rnn_reset_kernel<<<1, 256>>>();
    rnn_scan_kernel<<<NCTA, TPB>>>(X, Wi, bi, Wh, bh, Wo, bo, out);
}

// round 10
// speedup vs baseline: 9.2257x; 1.0516x over previous
#include <cuda_runtime.h>
#include <math.h>

// Problem constants
#define T_STEPS 16384
#define HID     1024
#define INP     256
#define NLAB    32

#define NCTA    64           // persistent CTAs (halve straggler/poller count)
#define WPC     8            // warps per CTA (proven narrow-CTA shape)
#define TPB     (WPC * 32)   // 256
#define RPW     2            // rows per warp; NCTA*WPC*RPW == HID

// Hidden state words: fp32 h with mantissa LSB = 1-bit step tag
// tau(s) = (s>>1)&1. Double-buffered by parity s&1; stale content is from
// step s-2 whose tau differs -> LSB equality == ready. Naturally-aligned 4B
// accesses are single-copy atomic, so value+tag never tear; validity is
// in-word, so no fences anywhere. LSB clobber <= 2^-23 relative (absorbed by
// the contractive recurrence). Reset restores both buffers every launch.
__device__ unsigned g_hbuf[2][HID];

__device__ __forceinline__ uint4 ldv4(const unsigned* p) {
    uint4 v;
    asm volatile("ld.volatile.global.v4.u32 {%0,%1,%2,%3}, [%4];"
                 : "=r"(v.x), "=r"(v.y), "=r"(v.z), "=r"(v.w) : "l"(p));
    return v;
}
__device__ __forceinline__ void stx32(unsigned* p, unsigned v) {
    asm volatile("st.relaxed.gpu.global.u32 [%0], %1;" :: "l"(p), "r"(v) : "memory");
}
__device__ __forceinline__ float tanh_fast(float v) {
    float r;
    asm volatile("tanh.approx.f32 %0, %1;" : "=f"(r) : "f"(v));
    return r;
}

__global__ void rnn_reset_kernel() {
    int t = threadIdx.x;
    for (int i = t; i < HID; i += blockDim.x) {
        g_hbuf[0][i] = 0u;   // h0 = 0.0f, LSB 0 == tau(0): valid for step 0
        g_hbuf[1][i] = 1u;   // LSB 1 != tau(1)=0: step-1 consumers must wait
    }
}

__global__ void __launch_bounds__(TPB, 1) rnn_scan_kernel(
    const float* __restrict__ X,    // [T, 1, 256]
    const float* __restrict__ Wi,   // [1024, 256]
    const float* __restrict__ bi,   // [1024]
    const float* __restrict__ Wh,   // [1024, 1024]
    const float* __restrict__ bh,   // [1024]
    const float* __restrict__ Wo,   // [32, 1024]
    const float* __restrict__ bo,   // [32]
    float* __restrict__ out)        // [32] log-softmax
{
    const int t    = threadIdx.x;
    const int lane = t & 31;
    const int warp = t >> 5;
    const int r0   = blockIdx.x * (WPC * RPW) + 2 * warp;  // this warp's rows
    const int r1   = r0 + 1;

    // Double-buffered plain-float h staged per CTA. One barrier per step.
    __shared__ float sh[2][HID];

    // ---- Register-resident weights (held for all 16384 steps) ----
    // Lane l owns hidden columns (k/4)*128 + 4l + (k%4), k=0..31; one LDS.128
    // of h per group feeds BOTH rows' FMAs.
    float w0[32], w1[32];
    #pragma unroll
    for (int k = 0; k < 32; k++) {
        int col = (k >> 2) * 128 + 4 * lane + (k & 3);
        w0[k] = Wh[r0 * HID + col];
        w1[k] = Wh[r1 * HID + col];
    }
    float wi0[8], wi1[8];
    #pragma unroll
    for (int k = 0; k < 8; k++) {
        int col = (k >> 2) * 128 + 4 * lane + (k & 3);
        wi0[k] = Wi[r0 * INP + col];
        wi1[k] = Wi[r1 * INP + col];
    }
    const float bias0 = bi[r0] + bh[r0];
    const float bias1 = bi[r1] + bh[r1];

    // ---- 3-deep input pipeline: x0 = step s, x1 = step s+1 ----
    const float4* X4 = (const float4*)X;   // step s slice at X4[s*64 + ...]
    float4 x0a = X4[lane];            float4 x0b = X4[32 + lane];
    float4 x1a = X4[64 + lane];       float4 x1b = X4[96 + lane];

    for (int s = 0; s < T_STEPS; s++) {
        const int buf = s & 1;
        const unsigned tau = ((unsigned)s >> 1) & 1u;
        const unsigned* hb = g_hbuf[buf];

        // ---- Poll: one v4 load covers this thread's 4 contiguous words. ----
        uint4 v = ldv4(hb + 4 * t);

        // Prefetch x for step s+2 (two step-periods of DRAM cover).
        float4 x2a, x2b;
        x2a.x = x2a.y = x2a.z = x2a.w = 0.f;
        x2b = x2a;
        if (s + 2 < T_STEPS) {
            x2a = X4[(s + 2) * 64 + lane];
            x2b = X4[(s + 2) * 64 + 32 + lane];
        }

        // Input projection for THIS step (both rows) while poll is in flight.
        float a0 = (lane == 0) ? bias0 : 0.0f;
        float a1 = 0.f, a2 = 0.f, a3 = 0.f;
        float b0 = (lane == 0) ? bias1 : 0.0f;
        float b1 = 0.f, b2 = 0.f, b3 = 0.f;
        a0 = fmaf(wi0[0], x0a.x, a0);  a1 = fmaf(wi0[1], x0a.y, a1);
        a2 = fmaf(wi0[2], x0a.z, a2);  a3 = fmaf(wi0[3], x0a.w, a3);
        a0 = fmaf(wi0[4], x0b.x, a0);  a1 = fmaf(wi0[5], x0b.y, a1);
        a2 = fmaf(wi0[6], x0b.z, a2);  a3 = fmaf(wi0[7], x0b.w, a3);
        b0 = fmaf(wi1[0], x0a.x, b0);  b1 = fmaf(wi1[1], x0a.y, b1);
        b2 = fmaf(wi1[2], x0a.z, b2);  b3 = fmaf(wi1[3], x0a.w, b3);
        b0 = fmaf(wi1[4], x0b.x, b0);  b1 = fmaf(wi1[5], x0b.y, b1);
        b2 = fmaf(wi1[6], x0b.z, b2);  b3 = fmaf(wi1[7], x0b.w, b3);

        // Spin: re-issue the single v4 until all 4 LSBs match tau.
        while ((((v.x ^ tau) | (v.y ^ tau) | (v.z ^ tau) | (v.w ^ tau)) & 1u))
            v = ldv4(hb + 4 * t);

        // Deposit as one STS.128 (LSB noise stays in the value; absorbed).
        *(uint4*)&sh[buf][4 * t] = v;

        __syncthreads();   // the only barrier per step

        // ---- Recurrent GEMV: 8x LDS.128 feed BOTH rows (64 FMA). ----
        const float* hs = sh[buf];
        #pragma unroll
        for (int g = 0; g < 8; g++) {
            float4 h4 = *(const float4*)(hs + g * 128 + 4 * lane);
            a0 = fmaf(w0[4 * g + 0], h4.x, a0);
            a1 = fmaf(w0[4 * g + 1], h4.y, a1);
            a2 = fmaf(w0[4 * g + 2], h4.z, a2);
            a3 = fmaf(w0[4 * g + 3], h4.w, a3);
            b0 = fmaf(w1[4 * g + 0], h4.x, b0);
            b1 = fmaf(w1[4 * g + 1], h4.y, b1);
            b2 = fmaf(w1[4 * g + 2], h4.z, b2);
            b3 = fmaf(w1[4 * g + 3], h4.w, b3);
        }
        float accA = (a0 + a1) + (a2 + a3);
        float accB = (b0 + b1) + (b2 + b3);

        // Two interleaved butterflies (ILP; all lanes get both sums).
        #pragma unroll
        for (int off = 16; off > 0; off >>= 1) {
            accA += __shfl_xor_sync(0xffffffffu, accA, off);
            accB += __shfl_xor_sync(0xffffffffu, accB, off);
        }

        // Parallel publish: lane 0 -> row r0, lane 1 -> row r1 (coalesced).
        const unsigned ntau = (((unsigned)(s + 1)) >> 1) & 1u;
        if (lane < 2) {
            float hnew = tanh_fast(lane == 0 ? accA : accB);
            unsigned ub = (__float_as_uint(hnew) & ~1u) | ntau;
            stx32(&g_hbuf[buf ^ 1][r0 + lane], ub);
        }

        x0a = x1a; x0b = x1b;
        x1a = x2a; x1b = x2b;
    }

    // ---- Epilogue: CTA 0 computes logits + log_softmax on h_T ----
    if (blockIdx.x == 0) {
        const unsigned tauT = ((unsigned)T_STEPS >> 1) & 1u;   // buffer 0
        for (int j = t; j < HID; j += TPB) {
            unsigned vv;
            do {
                asm volatile("ld.volatile.global.u32 %0, [%1];"
                             : "=r"(vv) : "l"(&g_hbuf[0][j]));
            } while ((vv & 1u) != tauT);
            sh[0][j] = __uint_as_float(vv);
        }
        __syncthreads();

        int orow = t >> 3;      // 32 rows x 8 threads
        int sub  = t & 7;
        float acc = 0.0f;
        #pragma unroll 4
        for (int j = 0; j < HID / 8; j += 4) {
            int col = sub * (HID / 8) + j;
            float4 w4 = ((const float4*)Wo)[(orow * HID + col) >> 2];
            acc = fmaf(w4.x, sh[0][col + 0], acc);
            acc = fmaf(w4.y, sh[0][col + 1], acc);
            acc = fmaf(w4.z, sh[0][col + 2], acc);
            acc = fmaf(w4.w, sh[0][col + 3], acc);
        }
        acc += __shfl_down_sync(0xffffffffu, acc, 4);
        acc += __shfl_down_sync(0xffffffffu, acc, 2);
        acc += __shfl_down_sync(0xffffffffu, acc, 1);

        __shared__ float s_log[NLAB];
        if (sub == 0) s_log[orow] = acc + bo[orow];
        __syncthreads();

        if (t < NLAB) {
            float vl = s_log[t];
            float m = vl;
            #pragma unroll
            for (int off = 16; off > 0; off >>= 1)
                m = fmaxf(m, __shfl_xor_sync(0xffffffffu, m, off));
            float e = expf(vl - m);
            float ssum = e;
            #pragma unroll
            for (int off = 16; off > 0; off >>= 1)
                ssum += __shfl_xor_sync(0xffffffffu, ssum, off);
            out[t] = vl - m - logf(ssum);
        }
    }
}

extern "C" void kernel_launch(void* const* d_in, const int* in_sizes, int n_in,
                              void* d_out, int out_size) {
    const float* X  = (const float*)d_in[0];
    const float* Wi = (const float*)d_in[1];
    const float* bi = (const float*)d_in[2];
    const float* Wh = (const float*)d_in[3];
    const float* bh = (const float*)d_in[4];
    const float* Wo = (const float*)d_in[5];
    const float* bo = (const float*)d_in[6];
    float* out = (float*)d_out;

    rnn_reset_kernel<<<1, 256>>>();
    rnn_scan_kernel<<<NCTA, TPB>>>(X, Wi, bi, Wh, bh, Wo, bo, out);
}